// round 17
// baseline (speedup 1.0000x reference)
#include <cuda_runtime.h>
#include <cuda_bf16.h>
#include <math.h>
#include <stdint.h>

// Problem dims (fixed by the reference)
#define Dm    1024
#define Sm    1024
#define NB    2
#define NHm   16
#define DQm   64
#define DHm   4096
#define NL    6
#define MROWS (NB*Sm)

// ---------------- scratch (device globals; no allocations allowed) --------
__device__ float g_h  [(size_t)MROWS*Dm];
__device__ float g_q  [(size_t)MROWS*Dm];
__device__ float g_kb [(size_t)MROWS*Dm];
__device__ float g_vb [(size_t)MROWS*Dm];
__device__ float g_ctx[(size_t)MROWS*Dm];
__device__ float g_tmp[(size_t)MROWS*Dm];
__device__ float g_ff [(size_t)MROWS*DHm];

// ---------------- copy x -> h ---------------------------------------------
__global__ void __launch_bounds__(256) copy_kernel(float4* __restrict__ dst,
                                                   const float4* __restrict__ src)
{
    int i = blockIdx.x * 256 + threadIdx.x;
    dst[i] = src[i];
}

// ---------------- tensor-core helpers --------------------------------------
__device__ __forceinline__ uint32_t sptr(const void* p)
{
    return (uint32_t)__cvta_generic_to_shared(p);
}
__device__ __forceinline__ void ldsm4(uint32_t* r, uint32_t addr)
{
    asm volatile("ldmatrix.sync.aligned.m8n8.x4.shared.b16 {%0,%1,%2,%3}, [%4];"
                 : "=r"(r[0]), "=r"(r[1]), "=r"(r[2]), "=r"(r[3]) : "r"(addr));
}
__device__ __forceinline__ void ldsm4t(uint32_t* r, uint32_t addr)
{
    asm volatile("ldmatrix.sync.aligned.m8n8.x4.trans.shared.b16 {%0,%1,%2,%3}, [%4];"
                 : "=r"(r[0]), "=r"(r[1]), "=r"(r[2]), "=r"(r[3]) : "r"(addr));
}
__device__ __forceinline__ void mma16816(float* c, const uint32_t* a, const uint32_t* b)
{
    asm volatile("mma.sync.aligned.m16n8k16.row.col.f32.bf16.bf16.f32 "
                 "{%0,%1,%2,%3}, {%4,%5,%6,%7}, {%8,%9}, {%0,%1,%2,%3};"
                 : "+f"(c[0]), "+f"(c[1]), "+f"(c[2]), "+f"(c[3])
                 : "r"(a[0]), "r"(a[1]), "r"(a[2]), "r"(a[3]),
                   "r"(b[0]), "r"(b[1]));
}
__device__ __forceinline__ uint32_t packbf(float a, float b)
{
    uint32_t d;
    asm volatile("cvt.rn.bf16x2.f32 %0, %1, %2;" : "=r"(d) : "f"(b), "f"(a));
    return d;
}
__device__ __forceinline__ float bf16val(float x)
{
    return __bfloat162float(__float2bfloat16(x));
}

#define APAD 24
#define BPAD 136
#define SZ_A (128*APAD)
#define SZ_B (16*BPAD)

// ---------------- fused QKV (BM=128 body; weight/output selected per block) -
// grid (24, 16): blockIdx.x>>3 selects q/k/v; blockIdx.x&7 is the n-tile.
__global__ void __launch_bounds__(256) qkv_kernel(
    const float* __restrict__ A,
    const float* __restrict__ Bq, const float* __restrict__ Bk, const float* __restrict__ Bv,
    const float* __restrict__ bq, const float* __restrict__ bk, const float* __restrict__ bv,
    float* __restrict__ Cq, float* __restrict__ Ck, float* __restrict__ Cv)
{
    __shared__ __nv_bfloat16 Ahs[2][SZ_A];
    __shared__ __nv_bfloat16 Als[2][SZ_A];
    __shared__ __nv_bfloat16 Bhs[2][SZ_B];
    __shared__ __nv_bfloat16 Bls[2][SZ_B];

    const int sel = blockIdx.x >> 3;
    const float* B    = (sel == 0) ? Bq : (sel == 1) ? Bk : Bv;
    const float* bias = (sel == 0) ? bq : (sel == 1) ? bk : bv;
    float*       C    = (sel == 0) ? Cq : (sel == 1) ? Ck : Cv;

    const int tid  = threadIdx.x;
    const int wid  = tid >> 5, lane = tid & 31;
    const int wm   = wid >> 2;
    const int wn   = wid & 3;
    const int m0   = blockIdx.y * 128;
    const int n0   = (blockIdx.x & 7) * 128;
    const int N = Dm, K = Dm;

    const int arow = tid >> 2;
    const int acol = (tid & 3) << 2;
    const int brow = tid >> 5;
    const int bcol = (tid & 31) << 2;

    float acc[4][4][4];
#pragma unroll
    for (int i = 0; i < 4; i++)
#pragma unroll
        for (int j = 0; j < 4; j++)
#pragma unroll
            for (int p = 0; p < 4; p++) acc[i][j][p] = 0.f;

    float4 pa[2], pb[2];
#pragma unroll
    for (int p = 0; p < 2; p++) {
        pa[p] = *(const float4*)(A + (size_t)(m0 + arow + 64 * p) * K + acol);
        pb[p] = *(const float4*)(B + (size_t)(brow + 8 * p) * N + n0 + bcol);
    }

    const int nt = K >> 4;
    for (int it = 0; it < nt; it++) {
        __nv_bfloat16* Ah = Ahs[it & 1];
        __nv_bfloat16* Al = Als[it & 1];
        __nv_bfloat16* Bh = Bhs[it & 1];
        __nv_bfloat16* Bl = Bls[it & 1];

#pragma unroll
        for (int p = 0; p < 2; p++) {
            float va[4] = { pa[p].x, pa[p].y, pa[p].z, pa[p].w };
            float vb[4] = { pb[p].x, pb[p].y, pb[p].z, pb[p].w };
            int ar = (arow + 64 * p) * APAD + acol;
            int br = (brow + 8 * p) * BPAD + bcol;
#pragma unroll
            for (int e = 0; e < 4; e += 2) {
                float h0 = bf16val(va[e]),   h1 = bf16val(va[e+1]);
                *(uint32_t*)&Ah[ar + e] = packbf(h0, h1);
                *(uint32_t*)&Al[ar + e] = packbf(va[e] - h0, va[e+1] - h1);
                float g0 = bf16val(vb[e]),   g1 = bf16val(vb[e+1]);
                *(uint32_t*)&Bh[br + e] = packbf(g0, g1);
                *(uint32_t*)&Bl[br + e] = packbf(vb[e] - g0, vb[e+1] - g1);
            }
        }
        __syncthreads();

        if (it + 1 < nt) {
            int k0 = (it + 1) << 4;
#pragma unroll
            for (int p = 0; p < 2; p++) {
                pa[p] = *(const float4*)(A + (size_t)(m0 + arow + 64 * p) * K + k0 + acol);
                pb[p] = *(const float4*)(B + (size_t)(k0 + brow + 8 * p) * N + n0 + bcol);
            }
        }

        uint32_t ah[4][4], al[4][4], bh4[2][4], bl4[2][4];
        const int amr = lane & 15;
        const int akc = (lane >> 4) * 8;
#pragma unroll
        for (int mf = 0; mf < 4; mf++) {
            int r = (wm * 64 + mf * 16 + amr) * APAD + akc;
            ldsm4(ah[mf], sptr(Ah + r));
            ldsm4(al[mf], sptr(Al + r));
        }
#pragma unroll
        for (int n16 = 0; n16 < 2; n16++) {
            int off = amr * BPAD + wn * 32 + n16 * 16 + akc;
            ldsm4t(bh4[n16], sptr(Bh + off));
            ldsm4t(bl4[n16], sptr(Bl + off));
        }
#pragma unroll
        for (int mf = 0; mf < 4; mf++)
#pragma unroll
            for (int n16 = 0; n16 < 2; n16++)
#pragma unroll
                for (int j = 0; j < 2; j++) {
                    float* c = acc[mf][2 * n16 + j];
                    mma16816(c, ah[mf], &bh4[n16][2 * j]);
                    mma16816(c, ah[mf], &bl4[n16][2 * j]);
                    mma16816(c, al[mf], &bh4[n16][2 * j]);
                }
    }

#pragma unroll
    for (int mf = 0; mf < 4; mf++) {
        int r = m0 + wm * 64 + mf * 16 + (lane >> 2);
#pragma unroll
        for (int nf = 0; nf < 4; nf++) {
            int cc = n0 + wn * 32 + nf * 8 + 2 * (lane & 3);
            float bx = bias[cc], by = bias[cc + 1];
            *(float2*)(C + (size_t)r * N + cc) =
                make_float2(acc[mf][nf][0] + bx, acc[mf][nf][1] + by);
            *(float2*)(C + (size_t)(r + 8) * N + cc) =
                make_float2(acc[mf][nf][2] + bx, acc[mf][nf][3] + by);
        }
    }
}

// ---------------- GEMM (BM=64) — higher occupancy; used for Wo, W1, W2 ------
#define SZ_A64 (64*APAD)

__global__ void __launch_bounds__(256) gemm64_kernel(
    const float* __restrict__ A, const float* __restrict__ B,
    const float* __restrict__ bias, float* __restrict__ C,
    int M, int N, int K, int relu)
{
    __shared__ __nv_bfloat16 Ahs[2][SZ_A64];
    __shared__ __nv_bfloat16 Als[2][SZ_A64];
    __shared__ __nv_bfloat16 Bhs[2][SZ_B];
    __shared__ __nv_bfloat16 Bls[2][SZ_B];

    const int tid  = threadIdx.x;
    const int wid  = tid >> 5, lane = tid & 31;
    const int wm   = wid >> 2;          // 0..1, 32 rows each
    const int wn   = wid & 3;
    const int m0   = blockIdx.y * 64;
    const int n0   = blockIdx.x * 128;

    const int arow = tid >> 2;          // 0..63 (single pass)
    const int acol = (tid & 3) << 2;
    const int brow = tid >> 5;
    const int bcol = (tid & 31) << 2;

    float acc[2][4][4];
#pragma unroll
    for (int i = 0; i < 2; i++)
#pragma unroll
        for (int j = 0; j < 4; j++)
#pragma unroll
            for (int p = 0; p < 4; p++) acc[i][j][p] = 0.f;

    float4 pa;
    float4 pb[2];
    pa = *(const float4*)(A + (size_t)(m0 + arow) * K + acol);
#pragma unroll
    for (int p = 0; p < 2; p++)
        pb[p] = *(const float4*)(B + (size_t)(brow + 8 * p) * N + n0 + bcol);

    const int nt = K >> 4;
    for (int it = 0; it < nt; it++) {
        __nv_bfloat16* Ah = Ahs[it & 1];
        __nv_bfloat16* Al = Als[it & 1];
        __nv_bfloat16* Bh = Bhs[it & 1];
        __nv_bfloat16* Bl = Bls[it & 1];

        {
            float va[4] = { pa.x, pa.y, pa.z, pa.w };
            int ar = arow * APAD + acol;
#pragma unroll
            for (int e = 0; e < 4; e += 2) {
                float h0 = bf16val(va[e]), h1 = bf16val(va[e+1]);
                *(uint32_t*)&Ah[ar + e] = packbf(h0, h1);
                *(uint32_t*)&Al[ar + e] = packbf(va[e] - h0, va[e+1] - h1);
            }
        }
#pragma unroll
        for (int p = 0; p < 2; p++) {
            float vb[4] = { pb[p].x, pb[p].y, pb[p].z, pb[p].w };
            int br = (brow + 8 * p) * BPAD + bcol;
#pragma unroll
            for (int e = 0; e < 4; e += 2) {
                float g0 = bf16val(vb[e]), g1 = bf16val(vb[e+1]);
                *(uint32_t*)&Bh[br + e] = packbf(g0, g1);
                *(uint32_t*)&Bl[br + e] = packbf(vb[e] - g0, vb[e+1] - g1);
            }
        }
        __syncthreads();

        if (it + 1 < nt) {
            int k0 = (it + 1) << 4;
            pa = *(const float4*)(A + (size_t)(m0 + arow) * K + k0 + acol);
#pragma unroll
            for (int p = 0; p < 2; p++)
                pb[p] = *(const float4*)(B + (size_t)(k0 + brow + 8 * p) * N + n0 + bcol);
        }

        uint32_t ah[2][4], al[2][4], bh4[2][4], bl4[2][4];
        const int amr = lane & 15;
        const int akc = (lane >> 4) * 8;
#pragma unroll
        for (int mf = 0; mf < 2; mf++) {
            int r = (wm * 32 + mf * 16 + amr) * APAD + akc;
            ldsm4(ah[mf], sptr(Ah + r));
            ldsm4(al[mf], sptr(Al + r));
        }
#pragma unroll
        for (int n16 = 0; n16 < 2; n16++) {
            int off = amr * BPAD + wn * 32 + n16 * 16 + akc;
            ldsm4t(bh4[n16], sptr(Bh + off));
            ldsm4t(bl4[n16], sptr(Bl + off));
        }
#pragma unroll
        for (int mf = 0; mf < 2; mf++)
#pragma unroll
            for (int n16 = 0; n16 < 2; n16++)
#pragma unroll
                for (int j = 0; j < 2; j++) {
                    float* c = acc[mf][2 * n16 + j];
                    mma16816(c, ah[mf], &bh4[n16][2 * j]);
                    mma16816(c, ah[mf], &bl4[n16][2 * j]);
                    mma16816(c, al[mf], &bh4[n16][2 * j]);
                }
    }

#pragma unroll
    for (int mf = 0; mf < 2; mf++) {
        int r = m0 + wm * 32 + mf * 16 + (lane >> 2);
#pragma unroll
        for (int nf = 0; nf < 4; nf++) {
            int cc = n0 + wn * 32 + nf * 8 + 2 * (lane & 3);
            float bx = bias[cc], by = bias[cc + 1];
            float v0 = acc[mf][nf][0] + bx, v1 = acc[mf][nf][1] + by;
            float v2 = acc[mf][nf][2] + bx, v3 = acc[mf][nf][3] + by;
            if (relu) {
                v0 = fmaxf(v0, 0.f); v1 = fmaxf(v1, 0.f);
                v2 = fmaxf(v2, 0.f); v3 = fmaxf(v3, 0.f);
            }
            *(float2*)(C + (size_t)r * N + cc)       = make_float2(v0, v1);
            *(float2*)(C + (size_t)(r + 8) * N + cc) = make_float2(v2, v3);
        }
    }
}

// ---------------- tensor-core flash attention — round-8 passer, verbatim ----
#define QPAD 72
#define KVSZ (32*QPAD)

__global__ void __launch_bounds__(256) attn_tc_kernel(
    const float* __restrict__ Q, const float* __restrict__ K,
    const float* __restrict__ V, const unsigned char* __restrict__ mask,
    float* __restrict__ O)
{
    __shared__ __nv_bfloat16 Khs[2][KVSZ];
    __shared__ __nv_bfloat16 Kls[2][KVSZ];
    __shared__ __nv_bfloat16 Vhs[2][KVSZ];
    __shared__ __nv_bfloat16 Vls[2][KVSZ];

    const int tid = threadIdx.x, w = tid >> 5, lane = tid & 31;
    const int qt = blockIdx.x, h = blockIdx.y, b = blockIdx.z;
    const int qr0 = qt * 128;
    const size_t hoff = (size_t)h * DQm;

    const int gr = lane >> 2;
    const int gc = (lane & 3) * 2;

    uint32_t qfh[4][4], qfl[4][4];
    {
        size_t qrow0 = (size_t)(b * Sm + qr0 + w * 16 + gr) * Dm + hoff;
        size_t qrow1 = qrow0 + 8 * (size_t)Dm;
#pragma unroll
        for (int kf = 0; kf < 4; kf++) {
            float2 q00 = *(const float2*)(Q + qrow0 + kf * 16 + gc);
            float2 q10 = *(const float2*)(Q + qrow1 + kf * 16 + gc);
            float2 q01 = *(const float2*)(Q + qrow0 + kf * 16 + gc + 8);
            float2 q11 = *(const float2*)(Q + qrow1 + kf * 16 + gc + 8);
            float h0 = bf16val(q00.x), h1 = bf16val(q00.y);
            float h2 = bf16val(q10.x), h3 = bf16val(q10.y);
            float h4 = bf16val(q01.x), h5 = bf16val(q01.y);
            float h6 = bf16val(q11.x), h7 = bf16val(q11.y);
            qfh[kf][0] = packbf(h0, h1);
            qfh[kf][1] = packbf(h2, h3);
            qfh[kf][2] = packbf(h4, h5);
            qfh[kf][3] = packbf(h6, h7);
            qfl[kf][0] = packbf(q00.x - h0, q00.y - h1);
            qfl[kf][1] = packbf(q10.x - h2, q10.y - h3);
            qfl[kf][2] = packbf(q01.x - h4, q01.y - h5);
            qfl[kf][3] = packbf(q11.x - h6, q11.y - h7);
        }
    }

    float oacc[8][4];
#pragma unroll
    for (int nf = 0; nf < 8; nf++)
#pragma unroll
        for (int p = 0; p < 4; p++) oacc[nf][p] = 0.f;
    float mrow0 = -1e30f, mrow1 = -1e30f, lrow0 = 0.f, lrow1 = 0.f;

    const unsigned char* mp0 = mask + (size_t)(b * Sm + qr0 + w * 16 + gr) * Sm;
    const unsigned char* mp1 = mp0 + 8 * (size_t)Sm;

    const int sr  = tid >> 4;
    const int sc4 = (tid & 15) << 2;

    float4 pk[2], pv[2];
#pragma unroll
    for (int j = 0; j < 2; j++) {
        size_t gb = ((size_t)(b * Sm + sr + 16 * j)) * Dm + hoff + sc4;
        pk[j] = *(const float4*)(K + gb);
        pv[j] = *(const float4*)(V + gb);
    }

    const int NT = Sm / 32;
    for (int it = 0; it < NT; it++) {
        __nv_bfloat16* Kh = Khs[it & 1];
        __nv_bfloat16* Kl = Kls[it & 1];
        __nv_bfloat16* Vh = Vhs[it & 1];
        __nv_bfloat16* Vl = Vls[it & 1];

#pragma unroll
        for (int j = 0; j < 2; j++) {
            int off = (sr + 16 * j) * QPAD + sc4;
            float a[4] = { pk[j].x, pk[j].y, pk[j].z, pk[j].w };
            float c[4] = { pv[j].x, pv[j].y, pv[j].z, pv[j].w };
#pragma unroll
            for (int e = 0; e < 4; e += 2) {
                float h0 = bf16val(a[e]), h1 = bf16val(a[e+1]);
                *(uint32_t*)&Kh[off + e] = packbf(h0, h1);
                *(uint32_t*)&Kl[off + e] = packbf(a[e] - h0, a[e+1] - h1);
                float g0 = bf16val(c[e]), g1 = bf16val(c[e+1]);
                *(uint32_t*)&Vh[off + e] = packbf(g0, g1);
                *(uint32_t*)&Vl[off + e] = packbf(c[e] - g0, c[e+1] - g1);
            }
        }
        __syncthreads();

        if (it + 1 < NT) {
            int kt = (it + 1) * 32;
#pragma unroll
            for (int j = 0; j < 2; j++) {
                size_t gb = ((size_t)(b * Sm + kt + sr + 16 * j)) * Dm + hoff + sc4;
                pk[j] = *(const float4*)(K + gb);
                pv[j] = *(const float4*)(V + gb);
            }
        }

        const int kt = it * 32;

        float pf[4][4];
#pragma unroll
        for (int n16 = 0; n16 < 2; n16++) {
            float sa[4] = {0.f,0.f,0.f,0.f}, sb[4] = {0.f,0.f,0.f,0.f};
#pragma unroll
            for (int kf = 0; kf < 4; kf++) {
                uint32_t kh4[4], kl4[4];
                int off = (n16 * 16 + (lane >> 4) * 8 + (lane & 7)) * QPAD
                        + kf * 16 + ((lane >> 3) & 1) * 8;
                ldsm4(kh4, sptr(Kh + off));
                ldsm4(kl4, sptr(Kl + off));
                mma16816(sa, qfh[kf], &kh4[0]);
                mma16816(sa, qfh[kf], &kl4[0]);
                mma16816(sa, qfl[kf], &kh4[0]);
                mma16816(sb, qfh[kf], &kh4[2]);
                mma16816(sb, qfh[kf], &kl4[2]);
                mma16816(sb, qfl[kf], &kh4[2]);
            }
#pragma unroll
            for (int j = 0; j < 2; j++) {
                const float* s4 = j ? sb : sa;
                int nf = 2 * n16 + j;
                int c = kt + nf * 8 + gc;
                uchar2 m0 = *(const uchar2*)(mp0 + c);
                uchar2 m1 = *(const uchar2*)(mp1 + c);
                pf[nf][0] = m0.x ? -1e9f : s4[0] * 0.125f;
                pf[nf][1] = m0.y ? -1e9f : s4[1] * 0.125f;
                pf[nf][2] = m1.x ? -1e9f : s4[2] * 0.125f;
                pf[nf][3] = m1.y ? -1e9f : s4[3] * 0.125f;
            }
        }

        float mx0 = -1e30f, mx1 = -1e30f;
#pragma unroll
        for (int nf = 0; nf < 4; nf++) {
            mx0 = fmaxf(mx0, fmaxf(pf[nf][0], pf[nf][1]));
            mx1 = fmaxf(mx1, fmaxf(pf[nf][2], pf[nf][3]));
        }
        mx0 = fmaxf(mx0, __shfl_xor_sync(0xffffffffu, mx0, 1));
        mx0 = fmaxf(mx0, __shfl_xor_sync(0xffffffffu, mx0, 2));
        mx1 = fmaxf(mx1, __shfl_xor_sync(0xffffffffu, mx1, 1));
        mx1 = fmaxf(mx1, __shfl_xor_sync(0xffffffffu, mx1, 2));
        float mn0 = fmaxf(mrow0, mx0), mn1 = fmaxf(mrow1, mx1);
        float al0 = __expf(mrow0 - mn0), al1 = __expf(mrow1 - mn1);
        mrow0 = mn0; mrow1 = mn1;

        float ps0 = 0.f, ps1 = 0.f;
#pragma unroll
        for (int nf = 0; nf < 4; nf++) {
            pf[nf][0] = __expf(pf[nf][0] - mn0);
            pf[nf][1] = __expf(pf[nf][1] - mn0);
            pf[nf][2] = __expf(pf[nf][2] - mn1);
            pf[nf][3] = __expf(pf[nf][3] - mn1);
            ps0 += pf[nf][0] + pf[nf][1];
            ps1 += pf[nf][2] + pf[nf][3];
        }
        ps0 += __shfl_xor_sync(0xffffffffu, ps0, 1);
        ps0 += __shfl_xor_sync(0xffffffffu, ps0, 2);
        ps1 += __shfl_xor_sync(0xffffffffu, ps1, 1);
        ps1 += __shfl_xor_sync(0xffffffffu, ps1, 2);
        lrow0 = lrow0 * al0 + ps0;
        lrow1 = lrow1 * al1 + ps1;
#pragma unroll
        for (int nf = 0; nf < 8; nf++) {
            oacc[nf][0] *= al0; oacc[nf][1] *= al0;
            oacc[nf][2] *= al1; oacc[nf][3] *= al1;
        }

        uint32_t pAh[2][4], pAl[2][4];
#pragma unroll
        for (int kf = 0; kf < 2; kf++) {
            float a0 = pf[2*kf][0],   a1 = pf[2*kf][1];
            float a2 = pf[2*kf][2],   a3 = pf[2*kf][3];
            float b0 = pf[2*kf+1][0], b1 = pf[2*kf+1][1];
            float b2 = pf[2*kf+1][2], b3 = pf[2*kf+1][3];
            float h0 = bf16val(a0), h1 = bf16val(a1);
            float h2 = bf16val(a2), h3 = bf16val(a3);
            float h4 = bf16val(b0), h5 = bf16val(b1);
            float h6 = bf16val(b2), h7 = bf16val(b3);
            pAh[kf][0] = packbf(h0, h1);
            pAh[kf][1] = packbf(h2, h3);
            pAh[kf][2] = packbf(h4, h5);
            pAh[kf][3] = packbf(h6, h7);
            pAl[kf][0] = packbf(a0 - h0, a1 - h1);
            pAl[kf][1] = packbf(a2 - h2, a3 - h3);
            pAl[kf][2] = packbf(b0 - h4, b1 - h5);
            pAl[kf][3] = packbf(b2 - h6, b3 - h7);
        }

#pragma unroll
        for (int n16 = 0; n16 < 4; n16++) {
#pragma unroll
            for (int kf = 0; kf < 2; kf++) {
                uint32_t vh4[4], vl4[4];
                int off = (kf * 16 + (lane & 15)) * QPAD + n16 * 16 + (lane >> 4) * 8;
                ldsm4t(vh4, sptr(Vh + off));
                ldsm4t(vl4, sptr(Vl + off));
                float* c0 = oacc[2 * n16];
                float* c1 = oacc[2 * n16 + 1];
                mma16816(c0, pAh[kf], &vh4[0]);
                mma16816(c0, pAh[kf], &vl4[0]);
                mma16816(c0, pAl[kf], &vh4[0]);
                mma16816(c1, pAh[kf], &vh4[2]);
                mma16816(c1, pAh[kf], &vl4[2]);
                mma16816(c1, pAl[kf], &vh4[2]);
            }
        }
    }

    float inv0 = 1.0f / lrow0, inv1 = 1.0f / lrow1;
    size_t row0 = (size_t)(b * Sm + qr0 + w * 16 + gr) * Dm + hoff;
    size_t row1 = row0 + 8 * (size_t)Dm;
#pragma unroll
    for (int nf = 0; nf < 8; nf++) {
        int c = nf * 8 + gc;
        *(float2*)(O + row0 + c) = make_float2(oacc[nf][0] * inv0, oacc[nf][1] * inv0);
        *(float2*)(O + row1 + c) = make_float2(oacc[nf][2] * inv1, oacc[nf][3] * inv1);
    }
}

// ---------------- fused residual + LayerNorm -------------------------------
__global__ void __launch_bounds__(256) ln_res_kernel(
    const float* __restrict__ x, const float* __restrict__ t,
    const float* __restrict__ g, const float* __restrict__ be,
    float* __restrict__ out)
{
    const int row = blockIdx.x, tid = threadIdx.x;
    const int w = tid >> 5, lane = tid & 31;
    __shared__ float red[8];
    __shared__ float bcast;

    float4 a = ((const float4*)(x + (size_t)row * Dm))[tid];
    float4 bb = ((const float4*)(t + (size_t)row * Dm))[tid];
    float v0 = a.x + bb.x, v1 = a.y + bb.y, v2 = a.z + bb.z, v3 = a.w + bb.w;

    float s = v0 + v1 + v2 + v3;
#pragma unroll
    for (int off = 16; off; off >>= 1) s += __shfl_xor_sync(0xffffffffu, s, off);
    if (lane == 0) red[w] = s;
    __syncthreads();
    if (tid == 0) {
        float tot = 0.f;
#pragma unroll
        for (int i = 0; i < 8; i++) tot += red[i];
        bcast = tot * (1.0f / Dm);
    }
    __syncthreads();
    const float mean = bcast;

    float d0 = v0 - mean, d1 = v1 - mean, d2 = v2 - mean, d3 = v3 - mean;
    float ss = d0 * d0 + d1 * d1 + d2 * d2 + d3 * d3;
#pragma unroll
    for (int off = 16; off; off >>= 1) ss += __shfl_xor_sync(0xffffffffu, ss, off);
    if (lane == 0) red[w] = ss;
    __syncthreads();
    if (tid == 0) {
        float tot = 0.f;
#pragma unroll
        for (int i = 0; i < 8; i++) tot += red[i];
        bcast = rsqrtf(tot * (1.0f / Dm) + 1e-5f);
    }
    __syncthreads();
    const float rstd = bcast;

    const int c = tid * 4;
    float4 o;
    o.x = d0 * rstd * g[c + 0] + be[c + 0];
    o.y = d1 * rstd * g[c + 1] + be[c + 1];
    o.z = d2 * rstd * g[c + 2] + be[c + 2];
    o.w = d3 * rstd * g[c + 3] + be[c + 3];
    ((float4*)(out + (size_t)row * Dm))[tid] = o;
}

// ---------------- orchestration --------------------------------------------
extern "C" void kernel_launch(void* const* d_in, const int* in_sizes, int n_in,
                              void* d_out, int out_size)
{
    const float* x            = (const float*)d_in[0];
    const unsigned char* mask = (const unsigned char*)d_in[1];
    const float* Wq  = (const float*)d_in[2];
    const float* bq  = (const float*)d_in[3];
    const float* Wk  = (const float*)d_in[4];
    const float* bk  = (const float*)d_in[5];
    const float* Wv  = (const float*)d_in[6];
    const float* bv  = (const float*)d_in[7];
    const float* Wo  = (const float*)d_in[8];
    const float* bo  = (const float*)d_in[9];
    const float* ln1g = (const float*)d_in[10];
    const float* ln1b = (const float*)d_in[11];
    const float* W1  = (const float*)d_in[12];
    const float* b1  = (const float*)d_in[13];
    const float* W2  = (const float*)d_in[14];
    const float* b2  = (const float*)d_in[15];
    const float* ln2g = (const float*)d_in[16];
    const float* ln2b = (const float*)d_in[17];
    float* out = (float*)d_out;

    float *h, *q, *k, *v, *ctx, *tmp, *ff;
    cudaGetSymbolAddress((void**)&h,   g_h);
    cudaGetSymbolAddress((void**)&q,   g_q);
    cudaGetSymbolAddress((void**)&k,   g_kb);
    cudaGetSymbolAddress((void**)&v,   g_vb);
    cudaGetSymbolAddress((void**)&ctx, g_ctx);
    cudaGetSymbolAddress((void**)&tmp, g_tmp);
    cudaGetSymbolAddress((void**)&ff,  g_ff);

    copy_kernel<<<(MROWS * Dm / 4) / 256, 256>>>((float4*)h, (const float4*)x);

    dim3 gqkv(24, MROWS / 128);          // (24, 16) fused QKV -> 384 CTAs
    dim3 gW1(DHm / 128, MROWS / 64);     // (32, 32) W1 BM=64 -> 1024 CTAs
    dim3 g64(Dm / 128, MROWS / 64);      // (8, 32)  Wo / W2 (BM=64) -> 256 CTAs
    dim3 ga(Sm / 128, NHm, NB);          // (8, 16, 2)

    for (int l = 0; l < NL; l++) {
        qkv_kernel<<<gqkv, 256>>>(h,
            Wq + (size_t)l * Dm * Dm, Wk + (size_t)l * Dm * Dm, Wv + (size_t)l * Dm * Dm,
            bq + (size_t)l * Dm, bk + (size_t)l * Dm, bv + (size_t)l * Dm,
            q, k, v);

        attn_tc_kernel<<<ga, 256>>>(q, k, v, mask, ctx);

        gemm64_kernel<<<g64, 256>>>(ctx, Wo + (size_t)l * Dm * Dm,
                                    bo + (size_t)l * Dm, tmp, MROWS, Dm, Dm, 0);
        ln_res_kernel<<<MROWS, 256>>>(h, tmp, ln1g + (size_t)l * Dm, ln1b + (size_t)l * Dm, h);

        gemm64_kernel<<<gW1, 256>>>(h, W1 + (size_t)l * Dm * DHm,
                                    b1 + (size_t)l * DHm, ff, MROWS, DHm, Dm, 1);
        gemm64_kernel<<<g64, 256>>>(ff, W2 + (size_t)l * DHm * Dm,
                                    b2 + (size_t)l * Dm, tmp, MROWS, Dm, DHm, 0);
        ln_res_kernel<<<MROWS, 256>>>(h, tmp, ln2g + (size_t)l * Dm, ln2b + (size_t)l * Dm,
                                      (l == NL - 1) ? out : h);
    }
}